// round 1
// baseline (speedup 1.0000x reference)
#include <cuda_runtime.h>
#include <math.h>

#define Bv 2
#define Nv 10000
#define Ev 160000
#define Hv 128
#define ETv 8
#define BN (Bv*Nv)          // 20000
#define EPSv 1e-5f
#define RSQRT_H 0.08838834764831843f   // 1/sqrt(128)

// ---------------- scratch (device globals; no runtime allocation) ----------------
__device__ float    g_Q[BN*Hv];
__device__ float    g_K[BN*Hv];
__device__ float    g_V[BN*Hv];
__device__ float    g_Agg[BN*Hv];    // unnormalized aggregate, then normalized in place
__device__ float    g_Hmid[BN*Hv];
__device__ float    g_segsum[BN];
__device__ unsigned g_segmax[BN];
__device__ float    g_logits[Bv*Ev];
__device__ float    g_Ke[ETv*Hv];
__device__ float    g_Ve[ETv*Hv];
__device__ float    g_eL[ETv];

// ---------------- helpers ----------------
__device__ __forceinline__ unsigned enc_f(float f) {
    unsigned u = __float_as_uint(f);
    return (u & 0x80000000u) ? ~u : (u | 0x80000000u);
}
__device__ __forceinline__ float dec_f(unsigned u) {
    return __uint_as_float((u & 0x80000000u) ? (u ^ 0x80000000u) : ~u);
}
__device__ __forceinline__ void red_add_v4(float* p, float4 v) {
    asm volatile("red.global.add.v4.f32 [%0], {%1,%2,%3,%4};"
                 :: "l"(p), "f"(v.x), "f"(v.y), "f"(v.z), "f"(v.w) : "memory");
}

// ---------------- 0: zero scratch ----------------
__global__ void zero_init() {
    int i = blockIdx.x * blockDim.x + threadIdx.x;
    int stride = gridDim.x * blockDim.x;
    for (int j = i; j < BN*Hv; j += stride) g_Agg[j] = 0.0f;
    for (int j = i; j < BN; j += stride) { g_segsum[j] = 0.0f; g_segmax[j] = 0u; }
}

// ---------------- 1: edge-type projections (tiny) ----------------
__global__ void prep_edge(const float* __restrict__ eemb,
                          const float* __restrict__ Wk,
                          const float* __restrict__ Wv,
                          const float* __restrict__ We,
                          const float* __restrict__ be) {
    int t = threadIdx.x >> 7;      // 0..7
    int j = threadIdx.x & 127;     // 0..127
    float ake = 0.f, ave = 0.f;
    #pragma unroll 4
    for (int k = 0; k < Hv; k++) {
        float e = eemb[t*Hv + k];
        ake += e * Wk[k*Hv + j];
        ave += e * Wv[k*Hv + j];
    }
    g_Ke[t*Hv + j] = ake;
    g_Ve[t*Hv + j] = ave;
    if (j == 0) {
        float s = 0.f;
        for (int k = 0; k < Hv; k++) s += eemb[t*Hv + k] * We[k];
        g_eL[t] = s + be[0];
    }
}

// ---------------- 2: QKV GEMM  (M=BN, N=128, K=128), z selects Q/K/V ----------------
#define TM 64
#define KC 32
__global__ void __launch_bounds__(256)
gemm_qkv(const float* __restrict__ hidden, const float* __restrict__ temb,
         const float* __restrict__ Wq, const float* __restrict__ bq,
         const float* __restrict__ Wk, const float* __restrict__ bk,
         const float* __restrict__ Wv, const float* __restrict__ bv)
{
    int which = blockIdx.z;
    const float* W    = which == 0 ? Wq : (which == 1 ? Wk : Wv);
    const float* bias = which == 0 ? bq : (which == 1 ? bk : bv);
    float* out        = which == 0 ? g_Q : (which == 1 ? g_K : g_V);
    bool addT = (which < 2);

    __shared__ float As[TM][KC];
    __shared__ float Ws[KC][Hv];
    int tid = threadIdx.x;
    int tx = tid & 31, ty = tid >> 5;
    int row0 = blockIdx.x * TM;

    float acc[8][4];
    #pragma unroll
    for (int r = 0; r < 8; r++) { acc[r][0]=0.f; acc[r][1]=0.f; acc[r][2]=0.f; acc[r][3]=0.f; }

    for (int k0 = 0; k0 < Hv; k0 += KC) {
        #pragma unroll
        for (int t = 0; t < 2; t++) {
            int idx = tid + t*256;
            int r = idx >> 3; int kk = (idx & 7) * 4;
            int row = row0 + r;
            float4 a = make_float4(0.f,0.f,0.f,0.f);
            if (row < BN) {
                a = *(const float4*)&hidden[row*Hv + k0 + kk];
                if (addT) {
                    float4 b = *(const float4*)&temb[row*Hv + k0 + kk];
                    a.x += b.x; a.y += b.y; a.z += b.z; a.w += b.w;
                }
            }
            *(float4*)&As[r][kk] = a;
        }
        #pragma unroll
        for (int t = 0; t < 4; t++) {
            int idx = tid + t*256;
            int r = idx >> 5; int c = (idx & 31) * 4;
            *(float4*)&Ws[r][c] = *(const float4*)&W[(k0 + r)*Hv + c];
        }
        __syncthreads();
        #pragma unroll
        for (int k = 0; k < KC; k++) {
            float4 b = *(float4*)&Ws[k][tx*4];
            #pragma unroll
            for (int r = 0; r < 8; r++) {
                float a = As[ty*8 + r][k];
                acc[r][0] += a * b.x; acc[r][1] += a * b.y;
                acc[r][2] += a * b.z; acc[r][3] += a * b.w;
            }
        }
        __syncthreads();
    }
    float4 bi = *(const float4*)&bias[tx*4];
    #pragma unroll
    for (int r = 0; r < 8; r++) {
        int row = row0 + ty*8 + r;
        if (row < BN) {
            float4 o;
            o.x = acc[r][0] + bi.x; o.y = acc[r][1] + bi.y;
            o.z = acc[r][2] + bi.z; o.w = acc[r][3] + bi.w;
            *(float4*)&out[row*Hv + tx*4] = o;
        }
    }
}

// ---------------- 3: per-edge logits + segment max ----------------
__global__ void edge_logits(const int* __restrict__ eidx, const int* __restrict__ etype)
{
    int w = (blockIdx.x * blockDim.x + threadIdx.x) >> 5;
    int lane = threadIdx.x & 31;
    if (w >= Ev) return;
    int src = eidx[w];
    int tgt = eidx[Ev + w];
    int ty  = etype[w];
    float4 ke = *(const float4*)&g_Ke[ty*Hv + lane*4];
    float el = g_eL[ty];
    #pragma unroll
    for (int b = 0; b < Bv; b++) {
        float4 q  = *(const float4*)&g_Q[(b*Nv + tgt)*Hv + lane*4];
        float4 kk = *(const float4*)&g_K[(b*Nv + src)*Hv + lane*4];
        float s = q.x*(kk.x+ke.x) + q.y*(kk.y+ke.y) + q.z*(kk.z+ke.z) + q.w*(kk.w+ke.w);
        #pragma unroll
        for (int off = 16; off > 0; off >>= 1) s += __shfl_xor_sync(0xffffffffu, s, off);
        if (lane == 0) {
            float l = s * RSQRT_H + el;
            g_logits[b*Ev + w] = l;
            atomicMax(&g_segmax[b*Nv + tgt], enc_f(l));
        }
    }
}

// ---------------- 4: per-edge scatter (exp, segment sum, weighted V aggregate) ----------------
__global__ void edge_scatter(const int* __restrict__ eidx, const int* __restrict__ etype)
{
    int w = (blockIdx.x * blockDim.x + threadIdx.x) >> 5;
    int lane = threadIdx.x & 31;
    if (w >= Ev) return;
    int src = eidx[w];
    int tgt = eidx[Ev + w];
    int ty  = etype[w];
    float4 ve = *(const float4*)&g_Ve[ty*Hv + lane*4];
    #pragma unroll
    for (int b = 0; b < Bv; b++) {
        float lg = g_logits[b*Ev + w];
        float m  = dec_f(g_segmax[b*Nv + tgt]);
        float ex = expf(lg - m);
        if (lane == 0) atomicAdd(&g_segsum[b*Nv + tgt], ex);
        float4 v = *(const float4*)&g_V[(b*Nv + src)*Hv + lane*4];
        float4 add;
        add.x = ex * (v.x + ve.x); add.y = ex * (v.y + ve.y);
        add.z = ex * (v.z + ve.z); add.w = ex * (v.w + ve.w);
        red_add_v4(&g_Agg[(b*Nv + tgt)*Hv + lane*4], add);
    }
}

// ---------------- 5: normalize aggregate ----------------
__global__ void normalize_agg()
{
    int i = blockIdx.x * blockDim.x + threadIdx.x;   // one float4 per thread
    if (i >= BN*32) return;
    int node = i >> 5;
    float s = g_segsum[node];
    float inv = (s > 0.f) ? 1.f/s : 0.f;
    float4 v = *(float4*)&g_Agg[i*4];
    v.x *= inv; v.y *= inv; v.z *= inv; v.w *= inv;
    *(float4*)&g_Agg[i*4] = v;
}

// ---------------- 6: MLP GEMM1: silu([hidden,agg,temb] @ W1 + b1) ----------------
__global__ void __launch_bounds__(256)
gemm_mlp1(const float* __restrict__ hidden, const float* __restrict__ temb,
          const float* __restrict__ W1, const float* __restrict__ b1)
{
    __shared__ float As[TM][KC];
    __shared__ float Ws[KC][Hv];
    int tid = threadIdx.x;
    int tx = tid & 31, ty = tid >> 5;
    int row0 = blockIdx.x * TM;

    float acc[8][4];
    #pragma unroll
    for (int r = 0; r < 8; r++) { acc[r][0]=0.f; acc[r][1]=0.f; acc[r][2]=0.f; acc[r][3]=0.f; }

    for (int k0 = 0; k0 < 3*Hv; k0 += KC) {
        int srcsel = k0 >> 7;          // 0: hidden, 1: agg, 2: temb
        int off = k0 & 127;
        const float* S = srcsel == 0 ? hidden : (srcsel == 1 ? g_Agg : temb);
        #pragma unroll
        for (int t = 0; t < 2; t++) {
            int idx = tid + t*256;
            int r = idx >> 3; int kk = (idx & 7) * 4;
            int row = row0 + r;
            float4 a = make_float4(0.f,0.f,0.f,0.f);
            if (row < BN) a = *(const float4*)&S[row*Hv + off + kk];
            *(float4*)&As[r][kk] = a;
        }
        #pragma unroll
        for (int t = 0; t < 4; t++) {
            int idx = tid + t*256;
            int r = idx >> 5; int c = (idx & 31) * 4;
            *(float4*)&Ws[r][c] = *(const float4*)&W1[(k0 + r)*Hv + c];
        }
        __syncthreads();
        #pragma unroll
        for (int k = 0; k < KC; k++) {
            float4 b = *(float4*)&Ws[k][tx*4];
            #pragma unroll
            for (int r = 0; r < 8; r++) {
                float a = As[ty*8 + r][k];
                acc[r][0] += a * b.x; acc[r][1] += a * b.y;
                acc[r][2] += a * b.z; acc[r][3] += a * b.w;
            }
        }
        __syncthreads();
    }
    float4 bi = *(const float4*)&b1[tx*4];
    #pragma unroll
    for (int r = 0; r < 8; r++) {
        int row = row0 + ty*8 + r;
        if (row < BN) {
            float4 o;
            o.x = acc[r][0] + bi.x; o.y = acc[r][1] + bi.y;
            o.z = acc[r][2] + bi.z; o.w = acc[r][3] + bi.w;
            // silu
            o.x = o.x / (1.f + expf(-o.x));
            o.y = o.y / (1.f + expf(-o.y));
            o.z = o.z / (1.f + expf(-o.z));
            o.w = o.w / (1.f + expf(-o.w));
            *(float4*)&g_Hmid[row*Hv + tx*4] = o;
        }
    }
}

// ---------------- 7: GEMM2 + residual + LayerNorm ----------------
__global__ void __launch_bounds__(256)
gemm2_ln(const float* __restrict__ hidden,
         const float* __restrict__ W2, const float* __restrict__ b2,
         const float* __restrict__ gamma, const float* __restrict__ beta,
         float* __restrict__ out)
{
    __shared__ float As[TM][KC];
    __shared__ float Ws[KC][Hv];
    int tid = threadIdx.x;
    int tx = tid & 31, ty = tid >> 5;
    int row0 = blockIdx.x * TM;

    float acc[8][4];
    #pragma unroll
    for (int r = 0; r < 8; r++) { acc[r][0]=0.f; acc[r][1]=0.f; acc[r][2]=0.f; acc[r][3]=0.f; }

    for (int k0 = 0; k0 < Hv; k0 += KC) {
        #pragma unroll
        for (int t = 0; t < 2; t++) {
            int idx = tid + t*256;
            int r = idx >> 3; int kk = (idx & 7) * 4;
            int row = row0 + r;
            float4 a = make_float4(0.f,0.f,0.f,0.f);
            if (row < BN) a = *(const float4*)&g_Hmid[row*Hv + k0 + kk];
            *(float4*)&As[r][kk] = a;
        }
        #pragma unroll
        for (int t = 0; t < 4; t++) {
            int idx = tid + t*256;
            int r = idx >> 5; int c = (idx & 31) * 4;
            *(float4*)&Ws[r][c] = *(const float4*)&W2[(k0 + r)*Hv + c];
        }
        __syncthreads();
        #pragma unroll
        for (int k = 0; k < KC; k++) {
            float4 b = *(float4*)&Ws[k][tx*4];
            #pragma unroll
            for (int r = 0; r < 8; r++) {
                float a = As[ty*8 + r][k];
                acc[r][0] += a * b.x; acc[r][1] += a * b.y;
                acc[r][2] += a * b.z; acc[r][3] += a * b.w;
            }
        }
        __syncthreads();
    }

    float4 b2v = *(const float4*)&b2[tx*4];
    float4 gv  = *(const float4*)&gamma[tx*4];
    float4 bev = *(const float4*)&beta[tx*4];
    #pragma unroll
    for (int r = 0; r < 8; r++) {
        int row = row0 + ty*8 + r;
        if (row < BN) {
            float4 h4 = *(const float4*)&hidden[row*Hv + tx*4];
            float4 x;
            x.x = acc[r][0] + b2v.x + h4.x;
            x.y = acc[r][1] + b2v.y + h4.y;
            x.z = acc[r][2] + b2v.z + h4.z;
            x.w = acc[r][3] + b2v.w + h4.w;
            float s  = x.x + x.y + x.z + x.w;
            float ss = x.x*x.x + x.y*x.y + x.z*x.z + x.w*x.w;
            #pragma unroll
            for (int off = 16; off > 0; off >>= 1) {
                s  += __shfl_xor_sync(0xffffffffu, s, off);
                ss += __shfl_xor_sync(0xffffffffu, ss, off);
            }
            float mean = s * (1.f/128.f);
            float var  = ss * (1.f/128.f) - mean*mean;
            float rstd = rsqrtf(var + EPSv);
            float4 o;
            o.x = (x.x - mean)*rstd*gv.x + bev.x;
            o.y = (x.y - mean)*rstd*gv.y + bev.y;
            o.z = (x.z - mean)*rstd*gv.z + bev.z;
            o.w = (x.w - mean)*rstd*gv.w + bev.w;
            *(float4*)&out[row*Hv + tx*4] = o;
        }
    }
}

// ---------------- launch ----------------
extern "C" void kernel_launch(void* const* d_in, const int* in_sizes, int n_in,
                              void* d_out, int out_size)
{
    const float* hidden = (const float*)d_in[0];
    const float* temb   = (const float*)d_in[1];
    const int*   eidx   = (const int*)d_in[2];
    const int*   etype  = (const int*)d_in[3];
    const float* eemb   = (const float*)d_in[4];
    const float* Wq = (const float*)d_in[5];  const float* bq = (const float*)d_in[6];
    const float* Wk = (const float*)d_in[7];  const float* bk = (const float*)d_in[8];
    const float* Wv = (const float*)d_in[9];  const float* bv = (const float*)d_in[10];
    const float* We = (const float*)d_in[11]; const float* be = (const float*)d_in[12];
    const float* W1 = (const float*)d_in[13]; const float* b1 = (const float*)d_in[14];
    const float* W2 = (const float*)d_in[15]; const float* b2 = (const float*)d_in[16];
    const float* gamma = (const float*)d_in[17]; const float* beta = (const float*)d_in[18];
    float* out = (float*)d_out;

    zero_init<<<2560, 256>>>();
    prep_edge<<<1, 1024>>>(eemb, Wk, Wv, We, be);
    dim3 gq((BN + TM - 1)/TM, 1, 3);
    gemm_qkv<<<gq, 256>>>(hidden, temb, Wq, bq, Wk, bk, Wv, bv);
    edge_logits<<<Ev/8, 256>>>(eidx, etype);
    edge_scatter<<<Ev/8, 256>>>(eidx, etype);
    normalize_agg<<<(BN*32 + 255)/256, 256>>>();
    gemm_mlp1<<<(BN + TM - 1)/TM, 256>>>(hidden, temb, W1, b1);
    gemm2_ln<<<(BN + TM - 1)/TM, 256>>>(hidden, W2, b2, gamma, beta, out);
}

// round 2
// speedup vs baseline: 1.0439x; 1.0439x over previous
#include <cuda_runtime.h>
#include <math.h>

#define Bv 2
#define Nv 10000
#define Ev 160000
#define Hv 128
#define ETv 8
#define BN (Bv*Nv)          // 20000
#define EPSv 1e-5f
#define RSQRT_H 0.08838834764831843f   // 1/sqrt(128)

// ---------------- scratch (device globals; no runtime allocation) ----------------
__device__ float    g_Q[BN*Hv];
__device__ float    g_K[BN*Hv];
__device__ float    g_V[BN*Hv];
__device__ float    g_Agg[BN*Hv];    // unnormalized aggregate
__device__ float    g_Hmid[BN*Hv];
__device__ float    g_segsum[BN];
__device__ unsigned g_segmax[BN];
__device__ float    g_logits[Bv*Ev];
__device__ float    g_Ke[ETv*Hv];
__device__ float    g_Ve[ETv*Hv];
__device__ float    g_eL[ETv];

// ---------------- helpers ----------------
__device__ __forceinline__ unsigned enc_f(float f) {
    unsigned u = __float_as_uint(f);
    return (u & 0x80000000u) ? ~u : (u | 0x80000000u);
}
__device__ __forceinline__ float dec_f(unsigned u) {
    return __uint_as_float((u & 0x80000000u) ? (u ^ 0x80000000u) : ~u);
}
__device__ __forceinline__ void red_add_v4(float* p, float4 v) {
    asm volatile("red.global.add.v4.f32 [%0], {%1,%2,%3,%4};"
                 :: "l"(p), "f"(v.x), "f"(v.y), "f"(v.z), "f"(v.w) : "memory");
}
// packed f32x2 fma: d += a * b  (per 32-bit lane)
__device__ __forceinline__ void fma2(unsigned long long& d,
                                     unsigned long long a,
                                     unsigned long long b) {
    asm("fma.rn.f32x2 %0, %1, %2, %0;" : "+l"(d) : "l"(a), "l"(b));
}
__device__ __forceinline__ unsigned long long dup2(float v) {
    unsigned long long r; unsigned u = __float_as_uint(v);
    asm("mov.b64 %0, {%1, %1};" : "=l"(r) : "r"(u));
    return r;
}
__device__ __forceinline__ void unpack2(unsigned long long v, float& lo, float& hi) {
    unsigned a, b;
    asm("mov.b64 {%0, %1}, %2;" : "=r"(a), "=r"(b) : "l"(v));
    lo = __uint_as_float(a); hi = __uint_as_float(b);
}

// ---------------- 0: zero scratch ----------------
__global__ void zero_init() {
    int i = blockIdx.x * blockDim.x + threadIdx.x;
    int stride = gridDim.x * blockDim.x;
    for (int j = i; j < BN*Hv; j += stride) g_Agg[j] = 0.0f;
    for (int j = i; j < BN; j += stride) { g_segsum[j] = 0.0f; g_segmax[j] = 0u; }
}

// ---------------- 1: edge-type projections (tiny) ----------------
__global__ void prep_edge(const float* __restrict__ eemb,
                          const float* __restrict__ Wk,
                          const float* __restrict__ Wv,
                          const float* __restrict__ We,
                          const float* __restrict__ be) {
    int t = threadIdx.x >> 7;      // 0..7
    int j = threadIdx.x & 127;     // 0..127
    float ake = 0.f, ave = 0.f;
    #pragma unroll 4
    for (int k = 0; k < Hv; k++) {
        float e = eemb[t*Hv + k];
        ake += e * Wk[k*Hv + j];
        ave += e * Wv[k*Hv + j];
    }
    g_Ke[t*Hv + j] = ake;
    g_Ve[t*Hv + j] = ave;
    if (j == 0) {
        float s = 0.f;
        for (int k = 0; k < Hv; k++) s += eemb[t*Hv + k] * We[k];
        g_eL[t] = s + be[0];
    }
}

// ================= f32x2 GEMM framework =================
// Tile: 64 rows x 128 cols, 128 threads, 8x8 per thread.
// rg = tid>>4 (row group, 8 rows), cg = tid&15 (col group, 8 cols).
#define TM 64
#define KC 32
#define APAD 36   // As row stride in floats (KC+4) -> conflict-light stores, aligned loads

// Inner product over one staged KC-chunk.
__device__ __forceinline__ void mm_chunk(const float* As, const float* Ws,
                                         int r0, int c0,
                                         unsigned long long acc[8][4]) {
    #pragma unroll
    for (int k = 0; k < KC; k++) {
        ulonglong2 b0 = *(const ulonglong2*)&Ws[k*Hv + c0];
        ulonglong2 b1 = *(const ulonglong2*)&Ws[k*Hv + c0 + 4];
        #pragma unroll
        for (int r = 0; r < 8; r++) {
            unsigned long long aa = dup2(As[(r0 + r)*APAD + k]);
            fma2(acc[r][0], aa, b0.x);
            fma2(acc[r][1], aa, b0.y);
            fma2(acc[r][2], aa, b1.x);
            fma2(acc[r][3], aa, b1.y);
        }
    }
}

// Stage W chunk: W[(k0..k0+KC) x 128] -> Ws[KC][128]
__device__ __forceinline__ void load_w(const float* __restrict__ W, int k0,
                                       float* Ws, int tid) {
    #pragma unroll
    for (int i = 0; i < 8; i++) {
        int lin = tid + i*128;
        int wr = lin >> 5; int wc = (lin & 31) * 4;
        *(float4*)&Ws[wr*Hv + wc] = *(const float4*)&W[(k0 + wr)*Hv + wc];
    }
}

// ---------------- 2: QKV GEMM (z selects Q/K/V) ----------------
__global__ void __launch_bounds__(128)
gemm_qkv(const float* __restrict__ hidden, const float* __restrict__ temb,
         const float* __restrict__ Wq, const float* __restrict__ bq,
         const float* __restrict__ Wk, const float* __restrict__ bk,
         const float* __restrict__ Wv, const float* __restrict__ bv)
{
    int which = blockIdx.z;
    const float* W    = which == 0 ? Wq : (which == 1 ? Wk : Wv);
    const float* bias = which == 0 ? bq : (which == 1 ? bk : bv);
    float* out        = which == 0 ? g_Q : (which == 1 ? g_K : g_V);
    bool addT = (which < 2);

    __shared__ float As[TM*APAD];
    __shared__ float Ws[KC*Hv];
    int tid = threadIdx.x;
    int rg = tid >> 4, cg = tid & 15;
    int r0 = rg * 8, c0 = cg * 8;
    int row0 = blockIdx.x * TM;

    unsigned long long acc[8][4];
    #pragma unroll
    for (int r = 0; r < 8; r++)
        #pragma unroll
        for (int c = 0; c < 4; c++) acc[r][c] = 0ull;

    for (int k0 = 0; k0 < Hv; k0 += KC) {
        #pragma unroll
        for (int i = 0; i < 4; i++) {
            int lin = tid + i*128;
            int r = lin >> 3; int kk = (lin & 7) * 4;
            int row = row0 + r;
            float4 a = make_float4(0.f,0.f,0.f,0.f);
            if (row < BN) {
                a = *(const float4*)&hidden[row*Hv + k0 + kk];
                if (addT) {
                    float4 b = *(const float4*)&temb[row*Hv + k0 + kk];
                    a.x += b.x; a.y += b.y; a.z += b.z; a.w += b.w;
                }
            }
            *(float4*)&As[r*APAD + kk] = a;
        }
        load_w(W, k0, Ws, tid);
        __syncthreads();
        mm_chunk(As, Ws, r0, c0, acc);
        __syncthreads();
    }

    float4 bi0 = *(const float4*)&bias[c0];
    float4 bi1 = *(const float4*)&bias[c0 + 4];
    #pragma unroll
    for (int r = 0; r < 8; r++) {
        int row = row0 + r0 + r;
        if (row < BN) {
            float v0,v1,v2,v3,v4,v5,v6,v7;
            unpack2(acc[r][0], v0, v1); unpack2(acc[r][1], v2, v3);
            unpack2(acc[r][2], v4, v5); unpack2(acc[r][3], v6, v7);
            float4 o0 = make_float4(v0+bi0.x, v1+bi0.y, v2+bi0.z, v3+bi0.w);
            float4 o1 = make_float4(v4+bi1.x, v5+bi1.y, v6+bi1.z, v7+bi1.w);
            *(float4*)&out[row*Hv + c0]     = o0;
            *(float4*)&out[row*Hv + c0 + 4] = o1;
        }
    }
}

// ---------------- 3: per-edge logits + segment max ----------------
__global__ void edge_logits(const int* __restrict__ eidx, const int* __restrict__ etype)
{
    int w = (blockIdx.x * blockDim.x + threadIdx.x) >> 5;
    int lane = threadIdx.x & 31;
    if (w >= Ev) return;
    int src = eidx[w];
    int tgt = eidx[Ev + w];
    int ty  = etype[w];
    float4 ke = *(const float4*)&g_Ke[ty*Hv + lane*4];
    float el = g_eL[ty];
    #pragma unroll
    for (int b = 0; b < Bv; b++) {
        float4 q  = *(const float4*)&g_Q[(b*Nv + tgt)*Hv + lane*4];
        float4 kk = *(const float4*)&g_K[(b*Nv + src)*Hv + lane*4];
        float s = q.x*(kk.x+ke.x) + q.y*(kk.y+ke.y) + q.z*(kk.z+ke.z) + q.w*(kk.w+ke.w);
        #pragma unroll
        for (int off = 16; off > 0; off >>= 1) s += __shfl_xor_sync(0xffffffffu, s, off);
        if (lane == 0) {
            float l = s * RSQRT_H + el;
            g_logits[b*Ev + w] = l;
            atomicMax(&g_segmax[b*Nv + tgt], enc_f(l));
        }
    }
}

// ---------------- 4: per-edge scatter ----------------
__global__ void edge_scatter(const int* __restrict__ eidx, const int* __restrict__ etype)
{
    int w = (blockIdx.x * blockDim.x + threadIdx.x) >> 5;
    int lane = threadIdx.x & 31;
    if (w >= Ev) return;
    int src = eidx[w];
    int tgt = eidx[Ev + w];
    int ty  = etype[w];
    float4 ve = *(const float4*)&g_Ve[ty*Hv + lane*4];
    #pragma unroll
    for (int b = 0; b < Bv; b++) {
        float lg = g_logits[b*Ev + w];
        float m  = dec_f(g_segmax[b*Nv + tgt]);
        float ex = expf(lg - m);
        if (lane == 0) atomicAdd(&g_segsum[b*Nv + tgt], ex);
        float4 v = *(const float4*)&g_V[(b*Nv + src)*Hv + lane*4];
        float4 add;
        add.x = ex * (v.x + ve.x); add.y = ex * (v.y + ve.y);
        add.z = ex * (v.z + ve.z); add.w = ex * (v.w + ve.w);
        red_add_v4(&g_Agg[(b*Nv + tgt)*Hv + lane*4], add);
    }
}

// ---------------- 5: MLP GEMM1 (normalization of Agg fused into A-load) ----------------
__global__ void __launch_bounds__(128)
gemm_mlp1(const float* __restrict__ hidden, const float* __restrict__ temb,
          const float* __restrict__ W1, const float* __restrict__ b1)
{
    __shared__ float As[TM*APAD];
    __shared__ float Ws[KC*Hv];
    int tid = threadIdx.x;
    int rg = tid >> 4, cg = tid & 15;
    int r0 = rg * 8, c0 = cg * 8;
    int row0 = blockIdx.x * TM;

    unsigned long long acc[8][4];
    #pragma unroll
    for (int r = 0; r < 8; r++)
        #pragma unroll
        for (int c = 0; c < 4; c++) acc[r][c] = 0ull;

    for (int k0 = 0; k0 < 3*Hv; k0 += KC) {
        int srcsel = k0 >> 7;          // 0: hidden, 1: agg, 2: temb
        int off = k0 & 127;
        const float* S = srcsel == 0 ? hidden : (srcsel == 1 ? g_Agg : temb);
        #pragma unroll
        for (int i = 0; i < 4; i++) {
            int lin = tid + i*128;
            int r = lin >> 3; int kk = (lin & 7) * 4;
            int row = row0 + r;
            float4 a = make_float4(0.f,0.f,0.f,0.f);
            if (row < BN) {
                a = *(const float4*)&S[row*Hv + off + kk];
                if (srcsel == 1) {
                    float s = g_segsum[row];
                    float inv = (s > 0.f) ? 1.f/s : 0.f;
                    a.x *= inv; a.y *= inv; a.z *= inv; a.w *= inv;
                }
            }
            *(float4*)&As[r*APAD + kk] = a;
        }
        load_w(W1, k0, Ws, tid);
        __syncthreads();
        mm_chunk(As, Ws, r0, c0, acc);
        __syncthreads();
    }

    float4 bi0 = *(const float4*)&b1[c0];
    float4 bi1 = *(const float4*)&b1[c0 + 4];
    #pragma unroll
    for (int r = 0; r < 8; r++) {
        int row = row0 + r0 + r;
        if (row < BN) {
            float v[8];
            unpack2(acc[r][0], v[0], v[1]); unpack2(acc[r][1], v[2], v[3]);
            unpack2(acc[r][2], v[4], v[5]); unpack2(acc[r][3], v[6], v[7]);
            v[0]+=bi0.x; v[1]+=bi0.y; v[2]+=bi0.z; v[3]+=bi0.w;
            v[4]+=bi1.x; v[5]+=bi1.y; v[6]+=bi1.z; v[7]+=bi1.w;
            #pragma unroll
            for (int j = 0; j < 8; j++) v[j] = v[j] / (1.f + expf(-v[j]));
            *(float4*)&g_Hmid[row*Hv + c0]     = make_float4(v[0],v[1],v[2],v[3]);
            *(float4*)&g_Hmid[row*Hv + c0 + 4] = make_float4(v[4],v[5],v[6],v[7]);
        }
    }
}

// ---------------- 6: GEMM2 + residual + LayerNorm ----------------
__global__ void __launch_bounds__(128)
gemm2_ln(const float* __restrict__ hidden,
         const float* __restrict__ W2, const float* __restrict__ b2,
         const float* __restrict__ gamma, const float* __restrict__ beta,
         float* __restrict__ out)
{
    __shared__ float As[TM*APAD];
    __shared__ float Ws[KC*Hv];
    int tid = threadIdx.x;
    int rg = tid >> 4, cg = tid & 15;
    int r0 = rg * 8, c0 = cg * 8;
    int row0 = blockIdx.x * TM;

    unsigned long long acc[8][4];
    #pragma unroll
    for (int r = 0; r < 8; r++)
        #pragma unroll
        for (int c = 0; c < 4; c++) acc[r][c] = 0ull;

    for (int k0 = 0; k0 < Hv; k0 += KC) {
        #pragma unroll
        for (int i = 0; i < 4; i++) {
            int lin = tid + i*128;
            int r = lin >> 3; int kk = (lin & 7) * 4;
            int row = row0 + r;
            float4 a = make_float4(0.f,0.f,0.f,0.f);
            if (row < BN) a = *(const float4*)&g_Hmid[row*Hv + k0 + kk];
            *(float4*)&As[r*APAD + kk] = a;
        }
        load_w(W2, k0, Ws, tid);
        __syncthreads();
        mm_chunk(As, Ws, r0, c0, acc);
        __syncthreads();
    }

    float4 b20 = *(const float4*)&b2[c0];
    float4 b21 = *(const float4*)&b2[c0 + 4];
    float4 gv0 = *(const float4*)&gamma[c0];
    float4 gv1 = *(const float4*)&gamma[c0 + 4];
    float4 be0 = *(const float4*)&beta[c0];
    float4 be1 = *(const float4*)&beta[c0 + 4];

    #pragma unroll
    for (int r = 0; r < 8; r++) {
        int row = row0 + r0 + r;
        float x[8];
        if (row < BN) {
            float4 h0 = *(const float4*)&hidden[row*Hv + c0];
            float4 h1 = *(const float4*)&hidden[row*Hv + c0 + 4];
            float v[8];
            unpack2(acc[r][0], v[0], v[1]); unpack2(acc[r][1], v[2], v[3]);
            unpack2(acc[r][2], v[4], v[5]); unpack2(acc[r][3], v[6], v[7]);
            x[0] = v[0]+b20.x+h0.x; x[1] = v[1]+b20.y+h0.y;
            x[2] = v[2]+b20.z+h0.z; x[3] = v[3]+b20.w+h0.w;
            x[4] = v[4]+b21.x+h1.x; x[5] = v[5]+b21.y+h1.y;
            x[6] = v[6]+b21.z+h1.z; x[7] = v[7]+b21.w+h1.w;
        } else {
            #pragma unroll
            for (int j = 0; j < 8; j++) x[j] = 0.f;
        }
        float s = 0.f, ss = 0.f;
        #pragma unroll
        for (int j = 0; j < 8; j++) { s += x[j]; ss += x[j]*x[j]; }
        // reduce across the 16 threads (half-warp) holding this row
        #pragma unroll
        for (int off = 8; off > 0; off >>= 1) {
            s  += __shfl_xor_sync(0xffffffffu, s, off);
            ss += __shfl_xor_sync(0xffffffffu, ss, off);
        }
        if (row < BN) {
            float mean = s * (1.f/128.f);
            float var  = ss * (1.f/128.f) - mean*mean;
            float rstd = rsqrtf(var + EPSv);
            float4 o0, o1;
            o0.x = (x[0]-mean)*rstd*gv0.x + be0.x;
            o0.y = (x[1]-mean)*rstd*gv0.y + be0.y;
            o0.z = (x[2]-mean)*rstd*gv0.z + be0.z;
            o0.w = (x[3]-mean)*rstd*gv0.w + be0.w;
            o1.x = (x[4]-mean)*rstd*gv1.x + be1.x;
            o1.y = (x[5]-mean)*rstd*gv1.y + be1.y;
            o1.z = (x[6]-mean)*rstd*gv1.z + be1.z;
            o1.w = (x[7]-mean)*rstd*gv1.w + be1.w;
            *(float4*)&out[row*Hv + c0]     = o0;
            *(float4*)&out[row*Hv + c0 + 4] = o1;
        }
    }
}

// ---------------- launch ----------------
extern "C" void kernel_launch(void* const* d_in, const int* in_sizes, int n_in,
                              void* d_out, int out_size)
{
    const float* hidden = (const float*)d_in[0];
    const float* temb   = (const float*)d_in[1];
    const int*   eidx   = (const int*)d_in[2];
    const int*   etype  = (const int*)d_in[3];
    const float* eemb   = (const float*)d_in[4];
    const float* Wq = (const float*)d_in[5];  const float* bq = (const float*)d_in[6];
    const float* Wk = (const float*)d_in[7];  const float* bk = (const float*)d_in[8];
    const float* Wv = (const float*)d_in[9];  const float* bv = (const float*)d_in[10];
    const float* We = (const float*)d_in[11]; const float* be = (const float*)d_in[12];
    const float* W1 = (const float*)d_in[13]; const float* b1 = (const float*)d_in[14];
    const float* W2 = (const float*)d_in[15]; const float* b2 = (const float*)d_in[16];
    const float* gamma = (const float*)d_in[17]; const float* beta = (const float*)d_in[18];
    float* out = (float*)d_out;

    int gb = (BN + TM - 1)/TM;   // 313
    zero_init<<<2560, 256>>>();
    prep_edge<<<1, 1024>>>(eemb, Wk, Wv, We, be);
    dim3 gq(gb, 1, 3);
    gemm_qkv<<<gq, 128>>>(hidden, temb, Wq, bq, Wk, bk, Wv, bv);
    edge_logits<<<Ev/8, 256>>>(eidx, etype);
    edge_scatter<<<Ev/8, 256>>>(eidx, etype);
    gemm_mlp1<<<gb, 128>>>(hidden, temb, W1, b1);
    gemm2_ln<<<gb, 128>>>(hidden, W2, b2, gamma, beta, out);
}